// round 3
// baseline (speedup 1.0000x reference)
#include <cuda_runtime.h>
#include <math.h>

#define NN 10000
#define EE 160000
#define BB 16
#define HH 64
#define AA 8
#define LL 2
#define MSGIN 131
#define UPDIN 129

// ---------------- scratch (device globals) ----------------------------------
__device__ float g_h[NN * HH];
__device__ float g_agg[NN * HH];
__device__ float g_pool[BB * HH];
__device__ float g_cnt[BB];
__device__ float g_T1[NN * 512];
__device__ float g_T2[NN * 512];

__device__ __forceinline__ float silu_f(float x) { return x / (1.0f + expf(-x)); }

// ============================================================================
// Node-side TP core: thread = (nq = tid>>2, kq = tid&3). acc[16] per thread.
// s_W tile layout: [i][512] with col = j*64 + k.
// ============================================================================
__device__ __forceinline__ void node_tp_tile(float (&acc)[16], const float* s_in_row,
                                             const float* s_W, const float (&av)[8],
                                             int kbase, int ilen)
{
    for (int i = 0; i < ilen; ++i) {
        float m = s_in_row[i];
        const float* wrow = s_W + i * 512 + kbase;
#pragma unroll
        for (int j = 0; j < 8; ++j) {
            float c = m * av[j];
            float4 w0 = *(const float4*)(wrow + j * 64);
            float4 w1 = *(const float4*)(wrow + j * 64 + 4);
            float4 w2 = *(const float4*)(wrow + j * 64 + 8);
            float4 w3 = *(const float4*)(wrow + j * 64 + 12);
            acc[0]  = fmaf(c, w0.x, acc[0]);   acc[1]  = fmaf(c, w0.y, acc[1]);
            acc[2]  = fmaf(c, w0.z, acc[2]);   acc[3]  = fmaf(c, w0.w, acc[3]);
            acc[4]  = fmaf(c, w1.x, acc[4]);   acc[5]  = fmaf(c, w1.y, acc[5]);
            acc[6]  = fmaf(c, w1.z, acc[6]);   acc[7]  = fmaf(c, w1.w, acc[7]);
            acc[8]  = fmaf(c, w2.x, acc[8]);   acc[9]  = fmaf(c, w2.y, acc[9]);
            acc[10] = fmaf(c, w2.z, acc[10]);  acc[11] = fmaf(c, w2.w, acc[11]);
            acc[12] = fmaf(c, w3.x, acc[12]);  acc[13] = fmaf(c, w3.y, acc[13]);
            acc[14] = fmaf(c, w3.z, acc[14]);  acc[15] = fmaf(c, w3.w, acc[15]);
        }
    }
}

__device__ __forceinline__ void stage_w(float* s_W, const float* Wg, int ibase, int ilen)
{
    const float4* src = (const float4*)(Wg + (size_t)ibase * 512);
    float4* dst = (float4*)s_W;
    int n4 = ilen * 128;
    for (int idx = threadIdx.x; idx < n4; idx += 256) dst[idx] = src[idx];
}

// ================= nodeT kernel (unchanged) =================================
#define NT_OFF_W 0
#define NT_OFF_H 8320
#define NT_FLOATS (8320 + 4160)
#define NT_BYTES (NT_FLOATS * 4)

__global__ void __launch_bounds__(256, 2)
nodeT_kernel(int l, const float* __restrict__ anf, const float* __restrict__ Wm1)
{
    extern __shared__ float sm[];
    float* s_Wt = sm + NT_OFF_W;
    float* s_h  = sm + NT_OFF_H;

    int tid = threadIdx.x;
    int n0 = blockIdx.x * 64;
    const float* Wl = Wm1 + (size_t)l * MSGIN * 512;

    for (int idx = tid; idx < 64 * 65; idx += 256) {
        int node = idx / 65, i = idx - node * 65;
        int n = min(n0 + node, NN - 1);
        s_h[idx] = (i < 64) ? g_h[n * 64 + i] : anf[n];
    }

    int nq = tid >> 2;
    int cq = tid & 3;

    for (int cc = 0; cc < 8; ++cc) {
        int is_t1 = (cc < 4);
        int base_row = is_t1 ? 0 : 65;
        int c_base = (is_t1 ? cc : cc - 4) * 128;

        __syncthreads();
        for (int idx = tid; idx < 65 * 128; idx += 256) {
            int i = idx >> 7, cl = idx & 127;
            int c = c_base + cl;
            int j = c & 7, k = c >> 3;
            s_Wt[idx] = Wl[(size_t)(base_row + i) * 512 + j * 64 + k];
        }
        __syncthreads();

        float acc[32];
#pragma unroll
        for (int t = 0; t < 32; ++t) acc[t] = 0.0f;

        for (int i = 0; i < 65; ++i) {
            float h = s_h[nq * 65 + i];
            const float* wrow = s_Wt + i * 128;
#pragma unroll
            for (int t = 0; t < 8; ++t) {
                float4 w = *(const float4*)(wrow + (cq + 4 * t) * 4);
                acc[t * 4 + 0] = fmaf(h, w.x, acc[t * 4 + 0]);
                acc[t * 4 + 1] = fmaf(h, w.y, acc[t * 4 + 1]);
                acc[t * 4 + 2] = fmaf(h, w.z, acc[t * 4 + 2]);
                acc[t * 4 + 3] = fmaf(h, w.w, acc[t * 4 + 3]);
            }
        }

        int n = n0 + nq;
        if (n < NN) {
            float* dstp = (is_t1 ? g_T1 : g_T2) + (size_t)n * 512 + c_base;
#pragma unroll
            for (int t = 0; t < 8; ++t) {
                *(float4*)(dstp + (cq + 4 * t) * 4) =
                    make_float4(acc[t * 4 + 0], acc[t * 4 + 1], acc[t * 4 + 2], acc[t * 4 + 3]);
            }
        }
    }
}

// ================= msg kernel v3 ============================================
// 128 edges/block, 256 threads, 3 CTAs/SM. W2 staged 8 rows at a time.
#define M3_OFF_W    0          // 8*512 = 4096
#define M3_OFF_M1   4096       // 128*65 = 8320
#define M3_OFF_A    12416      // 128*8 = 1024
#define M3_OFF_WAMF 13440      // 512
#define M3_OFF_B1   13952      // 64
#define M3_OFF_B2   14016      // 64
#define M3_OFF_IDX  14080      // 256 ints
#define M3_FLOATS   14336
#define M3_BYTES    (M3_FLOATS * 4)

__global__ void __launch_bounds__(256, 3)
msg_kernel_v3(int l, const int* __restrict__ edge_index, const float* __restrict__ edge_attr,
              const float* __restrict__ amf,
              const float* __restrict__ Wm1, const float* __restrict__ bm1,
              const float* __restrict__ Wm2, const float* __restrict__ bm2)
{
    extern __shared__ float sm[];
    float* s_W2   = sm + M3_OFF_W;
    float* s_m1   = sm + M3_OFF_M1;
    float* s_a    = sm + M3_OFF_A;
    float* s_wamf = sm + M3_OFF_WAMF;
    float* s_b1   = sm + M3_OFF_B1;
    float* s_b2   = sm + M3_OFF_B2;
    int*   s_src  = (int*)(sm + M3_OFF_IDX);
    int*   s_dst  = s_src + 128;

    int tid = threadIdx.x;
    int e_abs0 = blockIdx.x * 128;
    const float* W1l = Wm1 + (size_t)l * MSGIN * 512;
    const float* W2l = Wm2 + (size_t)l * 64 * 512;

    if (tid < 128) {
        s_src[tid] = edge_index[e_abs0 + tid];
        s_dst[tid] = edge_index[EE + e_abs0 + tid];
    }
    for (int idx = tid; idx < 1024; idx += 256)
        s_a[idx] = edge_attr[(size_t)e_abs0 * 8 + idx];
    for (int idx = tid; idx < 512; idx += 256) {
        int k = idx >> 3, j = idx & 7;
        s_wamf[idx] = W1l[(size_t)130 * 512 + j * 64 + k];
    }
    if (tid < 64) {
        s_b1[tid] = bm1[l * 64 + tid];
        s_b2[tid] = bm2[l * 64 + tid];
    }
    __syncthreads();

    int e  = tid >> 1;       // edge 0..127
    int kh = tid & 1;        // k-half
    int kbase = kh * 32;
    int d  = s_dst[e];
    int sn = s_src[e];

    // ---- Phase A: m1 = silu(b1 + sum_j a_j*(T1[d]+T2[s]) + amf*sum_j a_j*Wamf)
    {
        float amfv = amf[e_abs0 + e];
        float a[8], am[8];
#pragma unroll
        for (int j = 0; j < 8; ++j) {
            a[j] = s_a[e * 8 + j];
            am[j] = a[j] * amfv;
        }
        const float4* T1p = (const float4*)(g_T1 + (size_t)d * 512 + kbase * 8);
        const float4* T2p = (const float4*)(g_T2 + (size_t)sn * 512 + kbase * 8);
        const float4* Wam = (const float4*)(s_wamf + kbase * 8);

#pragma unroll 8
        for (int kk = 0; kk < 32; ++kk) {
            float4 p0 = T1p[kk * 2], p1 = T1p[kk * 2 + 1];
            float4 q0 = T2p[kk * 2], q1 = T2p[kk * 2 + 1];
            float4 w0 = Wam[kk * 2], w1 = Wam[kk * 2 + 1];
            float r = s_b1[kbase + kk];
            r = fmaf(a[0], p0.x + q0.x, r);
            r = fmaf(a[1], p0.y + q0.y, r);
            r = fmaf(a[2], p0.z + q0.z, r);
            r = fmaf(a[3], p0.w + q0.w, r);
            r = fmaf(a[4], p1.x + q1.x, r);
            r = fmaf(a[5], p1.y + q1.y, r);
            r = fmaf(a[6], p1.z + q1.z, r);
            r = fmaf(a[7], p1.w + q1.w, r);
            r = fmaf(am[0], w0.x, r);
            r = fmaf(am[1], w0.y, r);
            r = fmaf(am[2], w0.z, r);
            r = fmaf(am[3], w0.w, r);
            r = fmaf(am[4], w1.x, r);
            r = fmaf(am[5], w1.y, r);
            r = fmaf(am[6], w1.z, r);
            r = fmaf(am[7], w1.w, r);
            s_m1[e * 65 + kbase + kk] = silu_f(r);
        }
    }
    __syncthreads();

    // ---- Phase B: TP2, thread = 1 edge x 32 k
    float av[8];
#pragma unroll
    for (int j = 0; j < 8; ++j) av[j] = s_a[e * 8 + j];

    float acc[32];
#pragma unroll
    for (int t = 0; t < 32; ++t) acc[t] = s_b2[kbase + t];

    for (int ibase = 0; ibase < 64; ibase += 8) {
        stage_w(s_W2, W2l, ibase, 8);
        __syncthreads();

#pragma unroll
        for (int i = 0; i < 8; ++i) {
            float m = s_m1[e * 65 + ibase + i];
            const float* wrow = s_W2 + i * 512 + kbase;
#pragma unroll
            for (int j = 0; j < 8; ++j) {
                float c = m * av[j];
                const float* wj = wrow + j * 64;
#pragma unroll
                for (int t4 = 0; t4 < 8; ++t4) {
                    float4 w = *(const float4*)(wj + t4 * 4);
                    acc[t4 * 4 + 0] = fmaf(c, w.x, acc[t4 * 4 + 0]);
                    acc[t4 * 4 + 1] = fmaf(c, w.y, acc[t4 * 4 + 1]);
                    acc[t4 * 4 + 2] = fmaf(c, w.z, acc[t4 * 4 + 2]);
                    acc[t4 * 4 + 3] = fmaf(c, w.w, acc[t4 * 4 + 3]);
                }
            }
        }
        __syncthreads();
    }

    float* aggp = g_agg + (size_t)d * 64 + kbase;
#pragma unroll
    for (int t = 0; t < 32; ++t)
        atomicAdd(aggp + t, silu_f(acc[t]));
}

// ================= embed kernel v2: 64 nodes/block ==========================
// s_W 17*512=8704, s_in 64*20=1280, s_a 64*8=512
#define EM_OFF_W  0
#define EM_OFF_IN 8704
#define EM_OFF_A  (8704 + 1280)
#define EM_FLOATS (8704 + 1280 + 512)
#define EM_BYTES  (EM_FLOATS * 4)

__global__ void __launch_bounds__(256, 3)
embed_kernel_v2(const float* __restrict__ x, const float* __restrict__ anf,
                const float* __restrict__ node_attr,
                const float* __restrict__ W_emb, const float* __restrict__ b_emb)
{
    extern __shared__ float sm[];
    float* s_W  = sm + EM_OFF_W;
    float* s_in = sm + EM_OFF_IN;
    float* s_a  = sm + EM_OFF_A;

    int tid = threadIdx.x;
    int wid = tid >> 5, lane = tid & 31;
    int n0 = blockIdx.x * 64;

    stage_w(s_W, W_emb, 0, 17);
    for (int row = wid; row < 64; row += 8) {
        int n = min(n0 + row, NN - 1);
        if (lane < 17)
            s_in[row * 20 + lane] = (lane < 16) ? x[n * 16 + lane] : anf[n];
        if (lane < 8)
            s_a[row * 8 + lane] = node_attr[n * 8 + lane];
    }
    __syncthreads();

    int nq = tid >> 2, kq = tid & 3, kbase = kq * 16;
    float av[8];
#pragma unroll
    for (int j = 0; j < 8; ++j) av[j] = s_a[nq * 8 + j];

    float acc[16];
#pragma unroll
    for (int k = 0; k < 16; ++k) acc[k] = b_emb[kbase + k];

    node_tp_tile(acc, s_in + nq * 20, s_W, av, kbase, 17);

    int n = n0 + nq;
    if (n < NN) {
#pragma unroll
        for (int k = 0; k < 16; ++k) g_h[n * 64 + kbase + k] = acc[k];
    }
}

// ================= upd kernel v2: 64 nodes/block ============================
// s_W 16*512=8192, s_in 64*132=8448, s_mid 64*68=4352, s_a 512
#define UP_OFF_W   0
#define UP_OFF_IN  8192
#define UP_OFF_MID (8192 + 8448)
#define UP_OFF_A   (8192 + 8448 + 4352)
#define UP_FLOATS  (8192 + 8448 + 4352 + 512)
#define UP_BYTES   (UP_FLOATS * 4)

__global__ void __launch_bounds__(256, 2)
upd_kernel_v2(int l, const float* __restrict__ node_attr, const float* __restrict__ anf,
              const float* __restrict__ Wu1, const float* __restrict__ bu1,
              const float* __restrict__ Wu2, const float* __restrict__ bu2)
{
    extern __shared__ float sm[];
    float* s_W   = sm + UP_OFF_W;
    float* s_in  = sm + UP_OFF_IN;
    float* s_mid = sm + UP_OFF_MID;
    float* s_a   = sm + UP_OFF_A;

    int tid = threadIdx.x;
    int wid = tid >> 5, lane = tid & 31;
    int n0 = blockIdx.x * 64;

    for (int row = wid; row < 64; row += 8) {
        int n = min(n0 + row, NN - 1);
        float* dst = s_in + row * 132;
        for (int i = lane; i < UPDIN; i += 32) {
            float v;
            if (i < 64) v = g_h[n * 64 + i];
            else if (i == 64) v = anf[n];
            else v = g_agg[n * 64 + (i - 65)];
            dst[i] = v;
        }
        if (lane < 8) s_a[row * 8 + lane] = node_attr[n * 8 + lane];
    }

    int nq = tid >> 2, kq = tid & 3, kbase = kq * 16;
    const float* W1 = Wu1 + (size_t)l * UPDIN * 512;
    const float* W2 = Wu2 + (size_t)l * 64 * 512;

    __syncthreads();
    float av[8];
#pragma unroll
    for (int j = 0; j < 8; ++j) av[j] = s_a[nq * 8 + j];

    float acc[16];
#pragma unroll
    for (int k = 0; k < 16; ++k) acc[k] = bu1[l * 64 + kbase + k];

    for (int ibase = 0; ibase < UPDIN; ibase += 16) {
        int ilen = min(16, UPDIN - ibase);
        __syncthreads();
        stage_w(s_W, W1, ibase, ilen);
        __syncthreads();
        node_tp_tile(acc, s_in + nq * 132 + ibase, s_W, av, kbase, ilen);
    }

#pragma unroll
    for (int k = 0; k < 16; ++k)
        s_mid[nq * 68 + kbase + k] = silu_f(acc[k]);

#pragma unroll
    for (int k = 0; k < 16; ++k) acc[k] = bu2[l * 64 + kbase + k];

    for (int ibase = 0; ibase < 64; ibase += 16) {
        __syncthreads();
        stage_w(s_W, W2, ibase, 16);
        __syncthreads();
        node_tp_tile(acc, s_mid + nq * 68 + ibase, s_W, av, kbase, 16);
    }

    int n = n0 + nq;
    if (n < NN) {
#pragma unroll
        for (int k = 0; k < 16; ++k)
            g_h[n * 64 + kbase + k] += acc[k];
    }
}

// ================= pool kernel v2: 64 nodes/block ===========================
// s_W 16*512=8192, s_in 64*68=4352, s_mid 64*68=4352, s_a 512
#define PL_OFF_W   0
#define PL_OFF_IN  8192
#define PL_OFF_MID (8192 + 4352)
#define PL_OFF_A   (8192 + 4352 + 4352)
#define PL_FLOATS  (8192 + 4352 + 4352 + 512)
#define PL_BYTES   (PL_FLOATS * 4)

__global__ void __launch_bounds__(256, 3)
pool_kernel_v2(const float* __restrict__ node_attr, const int* __restrict__ batch,
               const float* __restrict__ Wp1, const float* __restrict__ bp1,
               const float* __restrict__ Wp2, const float* __restrict__ bp2)
{
    extern __shared__ float sm[];
    float* s_W   = sm + PL_OFF_W;
    float* s_in  = sm + PL_OFF_IN;
    float* s_mid = sm + PL_OFF_MID;
    float* s_a   = sm + PL_OFF_A;

    int tid = threadIdx.x;
    int wid = tid >> 5, lane = tid & 31;
    int n0 = blockIdx.x * 64;

    for (int row = wid; row < 64; row += 8) {
        int n = min(n0 + row, NN - 1);
        for (int i = lane; i < 64; i += 32)
            s_in[row * 68 + i] = g_h[n * 64 + i];
        if (lane < 8) s_a[row * 8 + lane] = node_attr[n * 8 + lane];
    }

    int nq = tid >> 2, kq = tid & 3, kbase = kq * 16;

    __syncthreads();
    float av[8];
#pragma unroll
    for (int j = 0; j < 8; ++j) av[j] = s_a[nq * 8 + j];

    float acc[16];
#pragma unroll
    for (int k = 0; k < 16; ++k) acc[k] = bp1[kbase + k];

    for (int ibase = 0; ibase < 64; ibase += 16) {
        __syncthreads();
        stage_w(s_W, Wp1, ibase, 16);
        __syncthreads();
        node_tp_tile(acc, s_in + nq * 68 + ibase, s_W, av, kbase, 16);
    }

#pragma unroll
    for (int k = 0; k < 16; ++k)
        s_mid[nq * 68 + kbase + k] = silu_f(acc[k]);

#pragma unroll
    for (int k = 0; k < 16; ++k) acc[k] = bp2[kbase + k];

    for (int ibase = 0; ibase < 64; ibase += 16) {
        __syncthreads();
        stage_w(s_W, Wp2, ibase, 16);
        __syncthreads();
        node_tp_tile(acc, s_mid + nq * 68 + ibase, s_W, av, kbase, 16);
    }

    int n = n0 + nq;
    if (n < NN) {
        int b = batch[n];
#pragma unroll
        for (int k = 0; k < 16; ++k)
            atomicAdd(&g_pool[b * 64 + kbase + k], acc[k]);
        if (kq == 0) atomicAdd(&g_cnt[b], 1.0f);
    }
}

// ---------------- final tiny post-pool MLP ---------------------------------
__global__ void final_kernel(const float* __restrict__ Wq1, const float* __restrict__ bq1,
                             const float* __restrict__ Wq2, const float* __restrict__ bq2,
                             float* __restrict__ out)
{
    int b = threadIdx.x;
    if (b >= BB) return;
    float c = g_cnt[b];
    if (c < 1.0f) c = 1.0f;
    float g[64];
#pragma unroll
    for (int k = 0; k < 64; ++k) g[k] = g_pool[b * 64 + k] / c;
    float o = bq2[0];
    for (int j = 0; j < 64; ++j) {
        float s = bq1[j];
#pragma unroll
        for (int k = 0; k < 64; ++k) s = fmaf(g[k], Wq1[k * 64 + j], s);
        o = fmaf(silu_f(s), Wq2[j], o);
    }
    out[b] = o;
}

// ---------------- launch ----------------------------------------------------
extern "C" void kernel_launch(void* const* d_in, const int* in_sizes, int n_in,
                              void* d_out, int out_size)
{
    const float* x         = (const float*)d_in[0];
    const int*   edge_index= (const int*)d_in[1];
    const float* edge_attr = (const float*)d_in[2];
    const float* node_attr = (const float*)d_in[3];
    const float* amf       = (const float*)d_in[4];
    const float* anf       = (const float*)d_in[5];
    const int*   batch     = (const int*)d_in[6];
    const float* W_emb     = (const float*)d_in[7];
    const float* b_emb     = (const float*)d_in[8];
    const float* Wm1       = (const float*)d_in[9];
    const float* bm1       = (const float*)d_in[10];
    const float* Wm2       = (const float*)d_in[11];
    const float* bm2       = (const float*)d_in[12];
    const float* Wu1       = (const float*)d_in[13];
    const float* bu1       = (const float*)d_in[14];
    const float* Wu2       = (const float*)d_in[15];
    const float* bu2       = (const float*)d_in[16];
    const float* Wp1       = (const float*)d_in[17];
    const float* bp1       = (const float*)d_in[18];
    const float* Wp2       = (const float*)d_in[19];
    const float* bp2       = (const float*)d_in[20];
    const float* Wq1       = (const float*)d_in[21];
    const float* bq1       = (const float*)d_in[22];
    const float* Wq2       = (const float*)d_in[23];
    const float* bq2       = (const float*)d_in[24];
    float* out = (float*)d_out;

    cudaFuncSetAttribute(msg_kernel_v3,   cudaFuncAttributeMaxDynamicSharedMemorySize, M3_BYTES);
    cudaFuncSetAttribute(nodeT_kernel,    cudaFuncAttributeMaxDynamicSharedMemorySize, NT_BYTES);
    cudaFuncSetAttribute(embed_kernel_v2, cudaFuncAttributeMaxDynamicSharedMemorySize, EM_BYTES);
    cudaFuncSetAttribute(upd_kernel_v2,   cudaFuncAttributeMaxDynamicSharedMemorySize, UP_BYTES);
    cudaFuncSetAttribute(pool_kernel_v2,  cudaFuncAttributeMaxDynamicSharedMemorySize, PL_BYTES);

    void* aggp = nullptr;  cudaGetSymbolAddress(&aggp, g_agg);
    void* poolp = nullptr; cudaGetSymbolAddress(&poolp, g_pool);
    void* cntp = nullptr;  cudaGetSymbolAddress(&cntp, g_cnt);

    int tblocks = (NN + 63) / 64;     // 157
    int eblocks = EE / 128;           // 1250

    embed_kernel_v2<<<tblocks, 256, EM_BYTES>>>(x, anf, node_attr, W_emb, b_emb);

    for (int l = 0; l < LL; ++l) {
        nodeT_kernel<<<tblocks, 256, NT_BYTES>>>(l, anf, Wm1);
        cudaMemsetAsync(aggp, 0, (size_t)NN * HH * sizeof(float));
        msg_kernel_v3<<<eblocks, 256, M3_BYTES>>>(l, edge_index, edge_attr, amf,
                                                  Wm1, bm1, Wm2, bm2);
        upd_kernel_v2<<<tblocks, 256, UP_BYTES>>>(l, node_attr, anf, Wu1, bu1, Wu2, bu2);
    }

    cudaMemsetAsync(poolp, 0, (size_t)BB * HH * sizeof(float));
    cudaMemsetAsync(cntp, 0, (size_t)BB * sizeof(float));
    pool_kernel_v2<<<tblocks, 256, PL_BYTES>>>(node_attr, batch, Wp1, bp1, Wp2, bp2);
    final_kernel<<<1, BB>>>(Wq1, bq1, Wq2, bq2, out);
}

// round 4
// speedup vs baseline: 1.6169x; 1.6169x over previous
#include <cuda_runtime.h>
#include <math.h>

#define NN 10000
#define EE 160000
#define BB 16
#define HH 64
#define AA 8
#define LL 2
#define MSGIN 131
#define UPDIN 129

// ---------------- scratch (device globals) ----------------------------------
__device__ float g_h[NN * HH];
__device__ float g_agg[NN * HH];
__device__ float g_pool[BB * HH];
__device__ float g_cnt[BB];
__device__ float g_T1[NN * 512];
__device__ float g_T2[NN * 512];

__device__ __forceinline__ float silu_f(float x) { return x / (1.0f + expf(-x)); }

// ============================================================================
// v4 node-side TP core. 128 threads/block, 64 nodes/block.
// thread = (ng = tid>>3 -> rows ng*4..ng*4+3, kq = tid&7 -> kbase = kq*8)
// acc[4][8] = 32 independent chains. W tile layout [i][512], col = j*64+k.
// ============================================================================
__device__ __forceinline__ void tp4(float (&acc)[4][8], const float* s_in, int stride,
                                    const float* s_W, const float (&av)[4][8],
                                    int nrow0, int kbase, int ilen)
{
    for (int i = 0; i < ilen; ++i) {
        float m0 = s_in[(nrow0 + 0) * stride + i];
        float m1 = s_in[(nrow0 + 1) * stride + i];
        float m2 = s_in[(nrow0 + 2) * stride + i];
        float m3 = s_in[(nrow0 + 3) * stride + i];
        const float* wrow = s_W + i * 512 + kbase;
#pragma unroll
        for (int j = 0; j < 8; ++j) {
            float4 wa = *(const float4*)(wrow + j * 64);
            float4 wb = *(const float4*)(wrow + j * 64 + 4);
            float w[8] = {wa.x, wa.y, wa.z, wa.w, wb.x, wb.y, wb.z, wb.w};
            float c0 = m0 * av[0][j];
            float c1 = m1 * av[1][j];
            float c2 = m2 * av[2][j];
            float c3 = m3 * av[3][j];
#pragma unroll
            for (int t = 0; t < 8; ++t) {
                acc[0][t] = fmaf(c0, w[t], acc[0][t]);
                acc[1][t] = fmaf(c1, w[t], acc[1][t]);
                acc[2][t] = fmaf(c2, w[t], acc[2][t]);
                acc[3][t] = fmaf(c3, w[t], acc[3][t]);
            }
        }
    }
}

__device__ __forceinline__ void stage_w128(float* s_W, const float* Wg, int ibase, int ilen)
{
    const float4* src = (const float4*)(Wg + (size_t)ibase * 512);
    float4* dst = (float4*)s_W;
    int n4 = ilen * 128;
    for (int idx = threadIdx.x; idx < n4; idx += 128) dst[idx] = src[idx];
}

// ================= nodeT kernel (round-2, unchanged) ========================
#define NT_OFF_W 0
#define NT_OFF_H 8320
#define NT_FLOATS (8320 + 4160)
#define NT_BYTES (NT_FLOATS * 4)

__global__ void __launch_bounds__(256, 2)
nodeT_kernel(int l, const float* __restrict__ anf, const float* __restrict__ Wm1)
{
    extern __shared__ float sm[];
    float* s_Wt = sm + NT_OFF_W;
    float* s_h  = sm + NT_OFF_H;

    int tid = threadIdx.x;
    int n0 = blockIdx.x * 64;
    const float* Wl = Wm1 + (size_t)l * MSGIN * 512;

    for (int idx = tid; idx < 64 * 65; idx += 256) {
        int node = idx / 65, i = idx - node * 65;
        int n = min(n0 + node, NN - 1);
        s_h[idx] = (i < 64) ? g_h[n * 64 + i] : anf[n];
    }

    int nq = tid >> 2;
    int cq = tid & 3;

    for (int cc = 0; cc < 8; ++cc) {
        int is_t1 = (cc < 4);
        int base_row = is_t1 ? 0 : 65;
        int c_base = (is_t1 ? cc : cc - 4) * 128;

        __syncthreads();
        for (int idx = tid; idx < 65 * 128; idx += 256) {
            int i = idx >> 7, cl = idx & 127;
            int c = c_base + cl;
            int j = c & 7, k = c >> 3;
            s_Wt[idx] = Wl[(size_t)(base_row + i) * 512 + j * 64 + k];
        }
        __syncthreads();

        float acc[32];
#pragma unroll
        for (int t = 0; t < 32; ++t) acc[t] = 0.0f;

        for (int i = 0; i < 65; ++i) {
            float h = s_h[nq * 65 + i];
            const float* wrow = s_Wt + i * 128;
#pragma unroll
            for (int t = 0; t < 8; ++t) {
                float4 w = *(const float4*)(wrow + (cq + 4 * t) * 4);
                acc[t * 4 + 0] = fmaf(h, w.x, acc[t * 4 + 0]);
                acc[t * 4 + 1] = fmaf(h, w.y, acc[t * 4 + 1]);
                acc[t * 4 + 2] = fmaf(h, w.z, acc[t * 4 + 2]);
                acc[t * 4 + 3] = fmaf(h, w.w, acc[t * 4 + 3]);
            }
        }

        int n = n0 + nq;
        if (n < NN) {
            float* dstp = (is_t1 ? g_T1 : g_T2) + (size_t)n * 512 + c_base;
#pragma unroll
            for (int t = 0; t < 8; ++t) {
                *(float4*)(dstp + (cq + 4 * t) * 4) =
                    make_float4(acc[t * 4 + 0], acc[t * 4 + 1], acc[t * 4 + 2], acc[t * 4 + 3]);
            }
        }
    }
}

// ================= msg kernel v2 (round-2, unchanged) =======================
#define M2_OFF_W    0          // 16*512 = 8192
#define M2_OFF_M1   8192       // 128*65 = 8320
#define M2_OFF_A    16512      // 128*8  = 1024
#define M2_OFF_WAMF 17536      // 512
#define M2_OFF_B1   18048      // 64
#define M2_OFF_B2   18112      // 64
#define M2_OFF_IDX  18176      // 256 ints
#define M2_FLOATS   18432
#define M2_BYTES    (M2_FLOATS * 4)

__global__ void __launch_bounds__(256, 2)
msg_kernel_v2(int l, const int* __restrict__ edge_index, const float* __restrict__ edge_attr,
              const float* __restrict__ amf,
              const float* __restrict__ Wm1, const float* __restrict__ bm1,
              const float* __restrict__ Wm2, const float* __restrict__ bm2)
{
    extern __shared__ float sm[];
    float* s_W2   = sm + M2_OFF_W;
    float* s_m1   = sm + M2_OFF_M1;
    float* s_a    = sm + M2_OFF_A;
    float* s_wamf = sm + M2_OFF_WAMF;
    float* s_b1   = sm + M2_OFF_B1;
    float* s_b2   = sm + M2_OFF_B2;
    int*   s_src  = (int*)(sm + M2_OFF_IDX);
    int*   s_dst  = s_src + 128;

    int tid = threadIdx.x;
    int e_abs0 = blockIdx.x * 128;
    const float* W1l = Wm1 + (size_t)l * MSGIN * 512;
    const float* W2l = Wm2 + (size_t)l * 64 * 512;

    if (tid < 128) {
        s_src[tid] = edge_index[e_abs0 + tid];
        s_dst[tid] = edge_index[EE + e_abs0 + tid];
    }
    for (int idx = tid; idx < 1024; idx += 256)
        s_a[idx] = edge_attr[(size_t)e_abs0 * 8 + idx];
    for (int idx = tid; idx < 512; idx += 256) {
        int k = idx >> 3, j = idx & 7;
        s_wamf[idx] = W1l[(size_t)130 * 512 + j * 64 + k];
    }
    if (tid < 64) {
        s_b1[tid] = bm1[l * 64 + tid];
        s_b2[tid] = bm2[l * 64 + tid];
    }
    __syncthreads();

    // ---- Phase A
    {
        int e = tid >> 1;
        int kh = tid & 1;
        int k0 = kh * 32;
        int d  = s_dst[e];
        int sn = s_src[e];
        float amfv = amf[e_abs0 + e];
        float a[8], am[8];
#pragma unroll
        for (int j = 0; j < 8; ++j) {
            a[j] = s_a[e * 8 + j];
            am[j] = a[j] * amfv;
        }
        const float4* T1p = (const float4*)(g_T1 + (size_t)d * 512 + k0 * 8);
        const float4* T2p = (const float4*)(g_T2 + (size_t)sn * 512 + k0 * 8);
        const float4* Wam = (const float4*)(s_wamf + k0 * 8);

#pragma unroll 8
        for (int kk = 0; kk < 32; ++kk) {
            float4 p0 = T1p[kk * 2], p1 = T1p[kk * 2 + 1];
            float4 q0 = T2p[kk * 2], q1 = T2p[kk * 2 + 1];
            float4 w0 = Wam[kk * 2], w1 = Wam[kk * 2 + 1];
            float r = s_b1[k0 + kk];
            r = fmaf(a[0], p0.x + q0.x, r);
            r = fmaf(a[1], p0.y + q0.y, r);
            r = fmaf(a[2], p0.z + q0.z, r);
            r = fmaf(a[3], p0.w + q0.w, r);
            r = fmaf(a[4], p1.x + q1.x, r);
            r = fmaf(a[5], p1.y + q1.y, r);
            r = fmaf(a[6], p1.z + q1.z, r);
            r = fmaf(a[7], p1.w + q1.w, r);
            r = fmaf(am[0], w0.x, r);
            r = fmaf(am[1], w0.y, r);
            r = fmaf(am[2], w0.z, r);
            r = fmaf(am[3], w0.w, r);
            r = fmaf(am[4], w1.x, r);
            r = fmaf(am[5], w1.y, r);
            r = fmaf(am[6], w1.z, r);
            r = fmaf(am[7], w1.w, r);
            s_m1[e * 65 + k0 + kk] = silu_f(r);
        }
    }
    __syncthreads();

    // ---- Phase B: thread = 4 edges x 8 k
    int eg = tid >> 3;
    int kg = tid & 7;
    int e0 = eg * 4;
    int kbase = kg * 8;

    float av[4][8];
#pragma unroll
    for (int s = 0; s < 4; ++s)
#pragma unroll
        for (int j = 0; j < 8; ++j) av[s][j] = s_a[(e0 + s) * 8 + j];

    float acc[4][8];
#pragma unroll
    for (int t = 0; t < 8; ++t) {
        float b = s_b2[kbase + t];
        acc[0][t] = b; acc[1][t] = b; acc[2][t] = b; acc[3][t] = b;
    }

    for (int ibase = 0; ibase < 64; ibase += 16) {
        {
            const float4* srcw = (const float4*)(W2l + (size_t)ibase * 512);
            float4* dstw = (float4*)s_W2;
            for (int idx = tid; idx < 16 * 128; idx += 256) dstw[idx] = srcw[idx];
        }
        __syncthreads();

        for (int i = 0; i < 16; ++i) {
            float m0 = s_m1[(e0 + 0) * 65 + ibase + i];
            float m1v = s_m1[(e0 + 1) * 65 + ibase + i];
            float m2 = s_m1[(e0 + 2) * 65 + ibase + i];
            float m3 = s_m1[(e0 + 3) * 65 + ibase + i];
            const float* wrow = s_W2 + i * 512 + kbase;
#pragma unroll
            for (int j = 0; j < 8; ++j) {
                float4 wa = *(const float4*)(wrow + j * 64);
                float4 wb = *(const float4*)(wrow + j * 64 + 4);
                float w[8] = {wa.x, wa.y, wa.z, wa.w, wb.x, wb.y, wb.z, wb.w};
                float c0 = m0  * av[0][j];
                float c1 = m1v * av[1][j];
                float c2 = m2  * av[2][j];
                float c3 = m3  * av[3][j];
#pragma unroll
                for (int t = 0; t < 8; ++t) {
                    acc[0][t] = fmaf(c0, w[t], acc[0][t]);
                    acc[1][t] = fmaf(c1, w[t], acc[1][t]);
                    acc[2][t] = fmaf(c2, w[t], acc[2][t]);
                    acc[3][t] = fmaf(c3, w[t], acc[3][t]);
                }
            }
        }
        __syncthreads();
    }

#pragma unroll
    for (int s = 0; s < 4; ++s) {
        int nd = s_dst[e0 + s];
#pragma unroll
        for (int t = 0; t < 8; ++t)
            atomicAdd(&g_agg[nd * 64 + kbase + t], silu_f(acc[s][t]));
    }
}

// ================= embed kernel v4 ==========================================
// s_W 17*512=8704, s_in 64*21=1344, s_a 512  -> 10560 floats = 42.2KB
#define E4_OFF_W  0
#define E4_OFF_IN 8704
#define E4_OFF_A  (8704 + 1344)
#define E4_FLOATS (8704 + 1344 + 512)
#define E4_BYTES  (E4_FLOATS * 4)

__global__ void __launch_bounds__(128, 2)
embed_kernel_v4(const float* __restrict__ x, const float* __restrict__ anf,
                const float* __restrict__ node_attr,
                const float* __restrict__ W_emb, const float* __restrict__ b_emb)
{
    extern __shared__ float sm[];
    float* s_W  = sm + E4_OFF_W;
    float* s_in = sm + E4_OFF_IN;
    float* s_a  = sm + E4_OFF_A;

    int tid = threadIdx.x;
    int wid = tid >> 5, lane = tid & 31;
    int n0 = blockIdx.x * 64;

    stage_w128(s_W, W_emb, 0, 17);
    for (int row = wid; row < 64; row += 4) {
        int n = min(n0 + row, NN - 1);
        if (lane < 17)
            s_in[row * 21 + lane] = (lane < 16) ? x[n * 16 + lane] : anf[n];
        if (lane < 8)
            s_a[row * 8 + lane] = node_attr[n * 8 + lane];
    }
    __syncthreads();

    int ng = tid >> 3, kq = tid & 7;
    int nrow0 = ng * 4, kbase = kq * 8;

    float av[4][8];
#pragma unroll
    for (int s = 0; s < 4; ++s)
#pragma unroll
        for (int j = 0; j < 8; ++j) av[s][j] = s_a[(nrow0 + s) * 8 + j];

    float acc[4][8];
#pragma unroll
    for (int t = 0; t < 8; ++t) {
        float b = b_emb[kbase + t];
        acc[0][t] = b; acc[1][t] = b; acc[2][t] = b; acc[3][t] = b;
    }

    tp4(acc, s_in, 21, s_W, av, nrow0, kbase, 17);

#pragma unroll
    for (int s = 0; s < 4; ++s) {
        int n = n0 + nrow0 + s;
        if (n < NN) {
#pragma unroll
            for (int t = 0; t < 8; ++t) g_h[n * 64 + kbase + t] = acc[s][t];
        }
    }
}

// ================= upd kernel v4 ============================================
// s_W 16*512=8192, s_in 64*133=8512, s_mid 64*67=4288, s_a 512 -> 21504 = 86KB
#define U4_OFF_W   0
#define U4_OFF_IN  8192
#define U4_OFF_MID (8192 + 8512)
#define U4_OFF_A   (8192 + 8512 + 4288)
#define U4_FLOATS  (8192 + 8512 + 4288 + 512)
#define U4_BYTES   (U4_FLOATS * 4)

__global__ void __launch_bounds__(128, 2)
upd_kernel_v4(int l, const float* __restrict__ node_attr, const float* __restrict__ anf,
              const float* __restrict__ Wu1, const float* __restrict__ bu1,
              const float* __restrict__ Wu2, const float* __restrict__ bu2)
{
    extern __shared__ float sm[];
    float* s_W   = sm + U4_OFF_W;
    float* s_in  = sm + U4_OFF_IN;
    float* s_mid = sm + U4_OFF_MID;
    float* s_a   = sm + U4_OFF_A;

    int tid = threadIdx.x;
    int wid = tid >> 5, lane = tid & 31;
    int n0 = blockIdx.x * 64;

    for (int row = wid; row < 64; row += 4) {
        int n = min(n0 + row, NN - 1);
        float* dst = s_in + row * 133;
        for (int i = lane; i < UPDIN; i += 32) {
            float v;
            if (i < 64) v = g_h[n * 64 + i];
            else if (i == 64) v = anf[n];
            else v = g_agg[n * 64 + (i - 65)];
            dst[i] = v;
        }
        if (lane < 8) s_a[row * 8 + lane] = node_attr[n * 8 + lane];
    }

    int ng = tid >> 3, kq = tid & 7;
    int nrow0 = ng * 4, kbase = kq * 8;
    const float* W1 = Wu1 + (size_t)l * UPDIN * 512;
    const float* W2 = Wu2 + (size_t)l * 64 * 512;

    __syncthreads();
    float av[4][8];
#pragma unroll
    for (int s = 0; s < 4; ++s)
#pragma unroll
        for (int j = 0; j < 8; ++j) av[s][j] = s_a[(nrow0 + s) * 8 + j];

    float acc[4][8];
#pragma unroll
    for (int t = 0; t < 8; ++t) {
        float b = bu1[l * 64 + kbase + t];
        acc[0][t] = b; acc[1][t] = b; acc[2][t] = b; acc[3][t] = b;
    }

    for (int ibase = 0; ibase < UPDIN; ibase += 16) {
        int ilen = min(16, UPDIN - ibase);
        __syncthreads();
        stage_w128(s_W, W1, ibase, ilen);
        __syncthreads();
        tp4(acc, s_in + ibase, 133, s_W, av, nrow0, kbase, ilen);
    }

#pragma unroll
    for (int s = 0; s < 4; ++s)
#pragma unroll
        for (int t = 0; t < 8; ++t)
            s_mid[(nrow0 + s) * 67 + kbase + t] = silu_f(acc[s][t]);

#pragma unroll
    for (int t = 0; t < 8; ++t) {
        float b = bu2[l * 64 + kbase + t];
        acc[0][t] = b; acc[1][t] = b; acc[2][t] = b; acc[3][t] = b;
    }

    for (int ibase = 0; ibase < 64; ibase += 16) {
        __syncthreads();
        stage_w128(s_W, W2, ibase, 16);
        __syncthreads();
        tp4(acc, s_mid + ibase, 67, s_W, av, nrow0, kbase, 16);
    }

#pragma unroll
    for (int s = 0; s < 4; ++s) {
        int n = n0 + nrow0 + s;
        if (n < NN) {
#pragma unroll
            for (int t = 0; t < 8; ++t)
                g_h[n * 64 + kbase + t] += acc[s][t];
        }
    }
}

// ================= pool kernel v4 ===========================================
// s_W 8192, s_in 64*67=4288, s_mid 4288, s_a 512 -> 17280 floats = 69.1KB
#define P4_OFF_W   0
#define P4_OFF_IN  8192
#define P4_OFF_MID (8192 + 4288)
#define P4_OFF_A   (8192 + 4288 + 4288)
#define P4_FLOATS  (8192 + 4288 + 4288 + 512)
#define P4_BYTES   (P4_FLOATS * 4)

__global__ void __launch_bounds__(128, 2)
pool_kernel_v4(const float* __restrict__ node_attr, const int* __restrict__ batch,
               const float* __restrict__ Wp1, const float* __restrict__ bp1,
               const float* __restrict__ Wp2, const float* __restrict__ bp2)
{
    extern __shared__ float sm[];
    float* s_W   = sm + P4_OFF_W;
    float* s_in  = sm + P4_OFF_IN;
    float* s_mid = sm + P4_OFF_MID;
    float* s_a   = sm + P4_OFF_A;

    int tid = threadIdx.x;
    int wid = tid >> 5, lane = tid & 31;
    int n0 = blockIdx.x * 64;

    for (int row = wid; row < 64; row += 4) {
        int n = min(n0 + row, NN - 1);
        for (int i = lane; i < 64; i += 32)
            s_in[row * 67 + i] = g_h[n * 64 + i];
        if (lane < 8) s_a[row * 8 + lane] = node_attr[n * 8 + lane];
    }

    int ng = tid >> 3, kq = tid & 7;
    int nrow0 = ng * 4, kbase = kq * 8;

    __syncthreads();
    float av[4][8];
#pragma unroll
    for (int s = 0; s < 4; ++s)
#pragma unroll
        for (int j = 0; j < 8; ++j) av[s][j] = s_a[(nrow0 + s) * 8 + j];

    float acc[4][8];
#pragma unroll
    for (int t = 0; t < 8; ++t) {
        float b = bp1[kbase + t];
        acc[0][t] = b; acc[1][t] = b; acc[2][t] = b; acc[3][t] = b;
    }

    for (int ibase = 0; ibase < 64; ibase += 16) {
        __syncthreads();
        stage_w128(s_W, Wp1, ibase, 16);
        __syncthreads();
        tp4(acc, s_in + ibase, 67, s_W, av, nrow0, kbase, 16);
    }

#pragma unroll
    for (int s = 0; s < 4; ++s)
#pragma unroll
        for (int t = 0; t < 8; ++t)
            s_mid[(nrow0 + s) * 67 + kbase + t] = silu_f(acc[s][t]);

#pragma unroll
    for (int t = 0; t < 8; ++t) {
        float b = bp2[kbase + t];
        acc[0][t] = b; acc[1][t] = b; acc[2][t] = b; acc[3][t] = b;
    }

    for (int ibase = 0; ibase < 64; ibase += 16) {
        __syncthreads();
        stage_w128(s_W, Wp2, ibase, 16);
        __syncthreads();
        tp4(acc, s_mid + ibase, 67, s_W, av, nrow0, kbase, 16);
    }

#pragma unroll
    for (int s = 0; s < 4; ++s) {
        int n = n0 + nrow0 + s;
        if (n < NN) {
            int b = batch[n];
#pragma unroll
            for (int t = 0; t < 8; ++t)
                atomicAdd(&g_pool[b * 64 + kbase + t], acc[s][t]);
            if (kq == 0) atomicAdd(&g_cnt[b], 1.0f);
        }
    }
}

// ---------------- final tiny post-pool MLP ---------------------------------
__global__ void final_kernel(const float* __restrict__ Wq1, const float* __restrict__ bq1,
                             const float* __restrict__ Wq2, const float* __restrict__ bq2,
                             float* __restrict__ out)
{
    int b = threadIdx.x;
    if (b >= BB) return;
    float c = g_cnt[b];
    if (c < 1.0f) c = 1.0f;
    float g[64];
#pragma unroll
    for (int k = 0; k < 64; ++k) g[k] = g_pool[b * 64 + k] / c;
    float o = bq2[0];
    for (int j = 0; j < 64; ++j) {
        float s = bq1[j];
#pragma unroll
        for (int k = 0; k < 64; ++k) s = fmaf(g[k], Wq1[k * 64 + j], s);
        o = fmaf(silu_f(s), Wq2[j], o);
    }
    out[b] = o;
}

// ---------------- launch ----------------------------------------------------
extern "C" void kernel_launch(void* const* d_in, const int* in_sizes, int n_in,
                              void* d_out, int out_size)
{
    const float* x         = (const float*)d_in[0];
    const int*   edge_index= (const int*)d_in[1];
    const float* edge_attr = (const float*)d_in[2];
    const float* node_attr = (const float*)d_in[3];
    const float* amf       = (const float*)d_in[4];
    const float* anf       = (const float*)d_in[5];
    const int*   batch     = (const int*)d_in[6];
    const float* W_emb     = (const float*)d_in[7];
    const float* b_emb     = (const float*)d_in[8];
    const float* Wm1       = (const float*)d_in[9];
    const float* bm1       = (const float*)d_in[10];
    const float* Wm2       = (const float*)d_in[11];
    const float* bm2       = (const float*)d_in[12];
    const float* Wu1       = (const float*)d_in[13];
    const float* bu1       = (const float*)d_in[14];
    const float* Wu2       = (const float*)d_in[15];
    const float* bu2       = (const float*)d_in[16];
    const float* Wp1       = (const float*)d_in[17];
    const float* bp1       = (const float*)d_in[18];
    const float* Wp2       = (const float*)d_in[19];
    const float* bp2       = (const float*)d_in[20];
    const float* Wq1       = (const float*)d_in[21];
    const float* bq1       = (const float*)d_in[22];
    const float* Wq2       = (const float*)d_in[23];
    const float* bq2       = (const float*)d_in[24];
    float* out = (float*)d_out;

    cudaFuncSetAttribute(msg_kernel_v2,   cudaFuncAttributeMaxDynamicSharedMemorySize, M2_BYTES);
    cudaFuncSetAttribute(nodeT_kernel,    cudaFuncAttributeMaxDynamicSharedMemorySize, NT_BYTES);
    cudaFuncSetAttribute(embed_kernel_v4, cudaFuncAttributeMaxDynamicSharedMemorySize, E4_BYTES);
    cudaFuncSetAttribute(upd_kernel_v4,   cudaFuncAttributeMaxDynamicSharedMemorySize, U4_BYTES);
    cudaFuncSetAttribute(pool_kernel_v4,  cudaFuncAttributeMaxDynamicSharedMemorySize, P4_BYTES);

    void* aggp = nullptr;  cudaGetSymbolAddress(&aggp, g_agg);
    void* poolp = nullptr; cudaGetSymbolAddress(&poolp, g_pool);
    void* cntp = nullptr;  cudaGetSymbolAddress(&cntp, g_cnt);

    int tblocks = (NN + 63) / 64;     // 157
    int eblocks = EE / 128;           // 1250

    embed_kernel_v4<<<tblocks, 128, E4_BYTES>>>(x, anf, node_attr, W_emb, b_emb);

    for (int l = 0; l < LL; ++l) {
        nodeT_kernel<<<tblocks, 256, NT_BYTES>>>(l, anf, Wm1);
        cudaMemsetAsync(aggp, 0, (size_t)NN * HH * sizeof(float));
        msg_kernel_v2<<<eblocks, 256, M2_BYTES>>>(l, edge_index, edge_attr, amf,
                                                  Wm1, bm1, Wm2, bm2);
        upd_kernel_v4<<<tblocks, 128, U4_BYTES>>>(l, node_attr, anf, Wu1, bu1, Wu2, bu2);
    }

    cudaMemsetAsync(poolp, 0, (size_t)BB * HH * sizeof(float));
    cudaMemsetAsync(cntp, 0, (size_t)BB * sizeof(float));
    pool_kernel_v4<<<tblocks, 128, P4_BYTES>>>(node_attr, batch, Wp1, bp1, Wp2, bp2);
    final_kernel<<<1, BB>>>(Wq1, bq1, Wq2, bq2, out);
}

// round 6
// speedup vs baseline: 2.0236x; 1.2515x over previous
#include <cuda_runtime.h>
#include <cuda_bf16.h>
#include <math.h>
#include <stdint.h>

#define NN 10000
#define EE 160000
#define BB 16
#define HH 64
#define AA 8
#define LL 2
#define MSGIN 131
#define UPDIN 129

// ---------------- scratch (device globals) ----------------------------------
__device__ float g_h[NN * HH];
__device__ float g_agg[NN * HH];
__device__ float g_pool[BB * HH];
__device__ float g_cnt[BB];
__device__ float g_T1[NN * 512];
__device__ float g_T2[NN * 512];

__device__ __forceinline__ float silu_f(float x) { return x / (1.0f + expf(-x)); }

// ---------------- warp MMA helper (generic sm_80+ PTX, no tcgen05) ----------
__device__ __forceinline__ void mma_bf16(float (&c)[4], const uint32_t (&a)[4],
                                         const uint32_t (&b)[2]) {
    asm volatile(
        "mma.sync.aligned.m16n8k16.row.col.f32.bf16.bf16.f32 "
        "{%0,%1,%2,%3}, {%4,%5,%6,%7}, {%8,%9}, {%0,%1,%2,%3};"
        : "+f"(c[0]), "+f"(c[1]), "+f"(c[2]), "+f"(c[3])
        : "r"(a[0]), "r"(a[1]), "r"(a[2]), "r"(a[3]), "r"(b[0]), "r"(b[1]));
}

__device__ __forceinline__ uint32_t pack2_bf16(__nv_bfloat16 lo16, __nv_bfloat16 hi16) {
    uint16_t a, b;
    memcpy(&a, &lo16, 2);
    memcpy(&b, &hi16, 2);
    return (uint32_t)a | ((uint32_t)b << 16);
}

// ============================================================================
// v4 node-side TP core (round-4, unchanged)
// ============================================================================
__device__ __forceinline__ void tp4(float (&acc)[4][8], const float* s_in, int stride,
                                    const float* s_W, const float (&av)[4][8],
                                    int nrow0, int kbase, int ilen)
{
    for (int i = 0; i < ilen; ++i) {
        float m0 = s_in[(nrow0 + 0) * stride + i];
        float m1 = s_in[(nrow0 + 1) * stride + i];
        float m2 = s_in[(nrow0 + 2) * stride + i];
        float m3 = s_in[(nrow0 + 3) * stride + i];
        const float* wrow = s_W + i * 512 + kbase;
#pragma unroll
        for (int j = 0; j < 8; ++j) {
            float4 wa = *(const float4*)(wrow + j * 64);
            float4 wb = *(const float4*)(wrow + j * 64 + 4);
            float w[8] = {wa.x, wa.y, wa.z, wa.w, wb.x, wb.y, wb.z, wb.w};
            float c0 = m0 * av[0][j];
            float c1 = m1 * av[1][j];
            float c2 = m2 * av[2][j];
            float c3 = m3 * av[3][j];
#pragma unroll
            for (int t = 0; t < 8; ++t) {
                acc[0][t] = fmaf(c0, w[t], acc[0][t]);
                acc[1][t] = fmaf(c1, w[t], acc[1][t]);
                acc[2][t] = fmaf(c2, w[t], acc[2][t]);
                acc[3][t] = fmaf(c3, w[t], acc[3][t]);
            }
        }
    }
}

__device__ __forceinline__ void stage_w128(float* s_W, const float* Wg, int ibase, int ilen)
{
    const float4* src = (const float4*)(Wg + (size_t)ibase * 512);
    float4* dst = (float4*)s_W;
    int n4 = ilen * 128;
    for (int idx = threadIdx.x; idx < n4; idx += 128) dst[idx] = src[idx];
}

// ================= nodeT kernel (unchanged) =================================
#define NT_OFF_W 0
#define NT_OFF_H 8320
#define NT_FLOATS (8320 + 4160)
#define NT_BYTES (NT_FLOATS * 4)

__global__ void __launch_bounds__(256, 2)
nodeT_kernel(int l, const float* __restrict__ anf, const float* __restrict__ Wm1)
{
    extern __shared__ float sm[];
    float* s_Wt = sm + NT_OFF_W;
    float* s_h  = sm + NT_OFF_H;

    int tid = threadIdx.x;
    int n0 = blockIdx.x * 64;
    const float* Wl = Wm1 + (size_t)l * MSGIN * 512;

    for (int idx = tid; idx < 64 * 65; idx += 256) {
        int node = idx / 65, i = idx - node * 65;
        int n = min(n0 + node, NN - 1);
        s_h[idx] = (i < 64) ? g_h[n * 64 + i] : anf[n];
    }

    int nq = tid >> 2;
    int cq = tid & 3;

    for (int cc = 0; cc < 8; ++cc) {
        int is_t1 = (cc < 4);
        int base_row = is_t1 ? 0 : 65;
        int c_base = (is_t1 ? cc : cc - 4) * 128;

        __syncthreads();
        for (int idx = tid; idx < 65 * 128; idx += 256) {
            int i = idx >> 7, cl = idx & 127;
            int c = c_base + cl;
            int j = c & 7, k = c >> 3;
            s_Wt[idx] = Wl[(size_t)(base_row + i) * 512 + j * 64 + k];
        }
        __syncthreads();

        float acc[32];
#pragma unroll
        for (int t = 0; t < 32; ++t) acc[t] = 0.0f;

        for (int i = 0; i < 65; ++i) {
            float h = s_h[nq * 65 + i];
            const float* wrow = s_Wt + i * 128;
#pragma unroll
            for (int t = 0; t < 8; ++t) {
                float4 w = *(const float4*)(wrow + (cq + 4 * t) * 4);
                acc[t * 4 + 0] = fmaf(h, w.x, acc[t * 4 + 0]);
                acc[t * 4 + 1] = fmaf(h, w.y, acc[t * 4 + 1]);
                acc[t * 4 + 2] = fmaf(h, w.z, acc[t * 4 + 2]);
                acc[t * 4 + 3] = fmaf(h, w.w, acc[t * 4 + 3]);
            }
        }

        int n = n0 + nq;
        if (n < NN) {
            float* dstp = (is_t1 ? g_T1 : g_T2) + (size_t)n * 512 + c_base;
#pragma unroll
            for (int t = 0; t < 8; ++t) {
                *(float4*)(dstp + (cq + 4 * t) * 4) =
                    make_float4(acc[t * 4 + 0], acc[t * 4 + 1], acc[t * 4 + 2], acc[t * 4 + 3]);
            }
        }
    }
}

// ================= msg kernel MMA: factored TP1 + warp-MMA TP2 ==============
// 128 edges/block, 256 threads (8 warps), 1 CTA/SM.
// bf16 tiles padded to 136-element rows (272B) => conflict-free fragment LDS.
// floats offsets:
#define MG_A_HI 0          // 128x136 bf16 = 8704 floats
#define MG_A_LO 8704
#define MG_B_HI 17408      // 64x136 bf16 = 4352 floats
#define MG_B_LO 21760
#define MG_M1   26112      // 128*65 fp32 = 8320
#define MG_A8   34432      // 128*8 = 1024
#define MG_WAMF 35456      // 512
#define MG_B1   35968      // 64
#define MG_B2   36032      // 64
#define MG_IDX  36096      // 256 ints
#define MG_FLOATS 36352
#define MG_BYTES (MG_FLOATS * 4)   // 145408 B

#define A_RS 272   // A row stride bytes
#define B_RS 272   // B row stride bytes

__global__ void __launch_bounds__(256, 1)
msg_kernel_mma(int l, const int* __restrict__ edge_index, const float* __restrict__ edge_attr,
               const float* __restrict__ amf,
               const float* __restrict__ Wm1, const float* __restrict__ bm1,
               const float* __restrict__ Wm2, const float* __restrict__ bm2)
{
    extern __shared__ float sm[];
    float* s_m1   = sm + MG_M1;
    float* s_a    = sm + MG_A8;
    float* s_wamf = sm + MG_WAMF;
    float* s_b1   = sm + MG_B1;
    float* s_b2   = sm + MG_B2;
    int*   s_src  = (int*)(sm + MG_IDX);
    int*   s_dst  = s_src + 128;
    char*  smc    = (char*)sm;
    char*  pAh    = smc + MG_A_HI * 4;
    char*  pAl    = smc + MG_A_LO * 4;
    char*  pBh    = smc + MG_B_HI * 4;
    char*  pBl    = smc + MG_B_LO * 4;

    int tid = threadIdx.x;
    int e_abs0 = blockIdx.x * 128;
    const float* W1l = Wm1 + (size_t)l * MSGIN * 512;
    const float* W2l = Wm2 + (size_t)l * 64 * 512;

    if (tid < 128) {
        s_src[tid] = edge_index[e_abs0 + tid];
        s_dst[tid] = edge_index[EE + e_abs0 + tid];
    }
    for (int idx = tid; idx < 1024; idx += 256)
        s_a[idx] = edge_attr[(size_t)e_abs0 * 8 + idx];
    for (int idx = tid; idx < 512; idx += 256) {
        int k = idx >> 3, j = idx & 7;
        s_wamf[idx] = W1l[(size_t)130 * 512 + j * 64 + k];
    }
    if (tid < 64) {
        s_b1[tid] = bm1[l * 64 + tid];
        s_b2[tid] = bm2[l * 64 + tid];
    }
    __syncthreads();

    // ---- Phase A: m1 = silu(b1 + sum_j a_j*(T1[d]+T2[s]) + amf*sum_j a_j*Wamf)
    {
        int e = tid >> 1;
        int kh = tid & 1;
        int k0 = kh * 32;
        int d  = s_dst[e];
        int sn = s_src[e];
        float amfv = amf[e_abs0 + e];
        float a[8], am[8];
#pragma unroll
        for (int j = 0; j < 8; ++j) {
            a[j] = s_a[e * 8 + j];
            am[j] = a[j] * amfv;
        }
        const float4* T1p = (const float4*)(g_T1 + (size_t)d * 512 + k0 * 8);
        const float4* T2p = (const float4*)(g_T2 + (size_t)sn * 512 + k0 * 8);
        const float4* Wam = (const float4*)(s_wamf + k0 * 8);

#pragma unroll 8
        for (int kk = 0; kk < 32; ++kk) {
            float4 p0 = T1p[kk * 2], p1 = T1p[kk * 2 + 1];
            float4 q0 = T2p[kk * 2], q1 = T2p[kk * 2 + 1];
            float4 w0 = Wam[kk * 2], w1 = Wam[kk * 2 + 1];
            float r = s_b1[k0 + kk];
            r = fmaf(a[0], p0.x + q0.x, r);
            r = fmaf(a[1], p0.y + q0.y, r);
            r = fmaf(a[2], p0.z + q0.z, r);
            r = fmaf(a[3], p0.w + q0.w, r);
            r = fmaf(a[4], p1.x + q1.x, r);
            r = fmaf(a[5], p1.y + q1.y, r);
            r = fmaf(a[6], p1.z + q1.z, r);
            r = fmaf(a[7], p1.w + q1.w, r);
            r = fmaf(am[0], w0.x, r);
            r = fmaf(am[1], w0.y, r);
            r = fmaf(am[2], w0.z, r);
            r = fmaf(am[3], w0.w, r);
            r = fmaf(am[4], w1.x, r);
            r = fmaf(am[5], w1.y, r);
            r = fmaf(am[6], w1.z, r);
            r = fmaf(am[7], w1.w, r);
            s_m1[e * 65 + k0 + kk] = silu_f(r);
        }
    }
    __syncthreads();

    // ---- Phase B: split-bf16 warp-MMA GEMM  D[128,64] = M1A[128,512] @ W2[512,64]
    int w = tid >> 5, lane = tid & 31;
    int g = lane >> 2, t = lane & 3;

    float acc[8][4];
#pragma unroll
    for (int nt = 0; nt < 8; ++nt)
#pragma unroll
        for (int q = 0; q < 4; ++q) acc[nt][q] = 0.0f;

    for (int c = 0; c < 4; ++c) {
        // build B chunk: B_nk[n][kl] = W2[(c*128+kl)][n]  (W2 flat [512][64])
        {
            int n = tid & 63;
            int klb = tid >> 6;   // 0..3
#pragma unroll 8
            for (int s = 0; s < 32; ++s) {
                int kl = klb + s * 4;
                float v = W2l[(size_t)(c * 128 + kl) * 64 + n];
                __nv_bfloat16 h = __float2bfloat16(v);
                __nv_bfloat16 lo = __float2bfloat16(v - __bfloat162float(h));
                *(__nv_bfloat16*)(pBh + n * B_RS + kl * 2) = h;
                *(__nv_bfloat16*)(pBl + n * B_RS + kl * 2) = lo;
            }
        }
        // build A chunk: A[e][kl] = m1[e][c*16 + (kl>>3)] * a[e][kl&7]
        {
            int e = tid >> 1, kh = tid & 1;
            float m1v[8], av8[8];
#pragma unroll
            for (int ii = 0; ii < 8; ++ii) m1v[ii] = s_m1[e * 65 + c * 16 + kh * 8 + ii];
#pragma unroll
            for (int j = 0; j < 8; ++j) av8[j] = s_a[e * 8 + j];
#pragma unroll 8
            for (int p = 0; p < 32; ++p) {
                int kl = kh * 64 + p * 2;
                float v0 = m1v[p >> 2] * av8[(2 * p) & 7];
                float v1 = m1v[p >> 2] * av8[(2 * p + 1) & 7];
                __nv_bfloat16 h0 = __float2bfloat16(v0);
                __nv_bfloat16 h1 = __float2bfloat16(v1);
                __nv_bfloat16 l0 = __float2bfloat16(v0 - __bfloat162float(h0));
                __nv_bfloat16 l1 = __float2bfloat16(v1 - __bfloat162float(h1));
                *(uint32_t*)(pAh + e * A_RS + kl * 2) = pack2_bf16(h0, h1);
                *(uint32_t*)(pAl + e * A_RS + kl * 2) = pack2_bf16(l0, l1);
            }
        }
        __syncthreads();

        // MMA over this chunk
        const char* rowAh0 = pAh + (w * 16 + g) * A_RS;
        const char* rowAh8 = pAh + (w * 16 + g + 8) * A_RS;
        const char* rowAl0 = pAl + (w * 16 + g) * A_RS;
        const char* rowAl8 = pAl + (w * 16 + g + 8) * A_RS;

#pragma unroll
        for (int kt = 0; kt < 8; ++kt) {
            int koff = (kt * 16 + 2 * t) * 2;
            uint32_t ah[4], al[4];
            ah[0] = *(const uint32_t*)(rowAh0 + koff);
            ah[1] = *(const uint32_t*)(rowAh8 + koff);
            ah[2] = *(const uint32_t*)(rowAh0 + koff + 16);
            ah[3] = *(const uint32_t*)(rowAh8 + koff + 16);
            al[0] = *(const uint32_t*)(rowAl0 + koff);
            al[1] = *(const uint32_t*)(rowAl8 + koff);
            al[2] = *(const uint32_t*)(rowAl0 + koff + 16);
            al[3] = *(const uint32_t*)(rowAl8 + koff + 16);
#pragma unroll
            for (int nt = 0; nt < 8; ++nt) {
                const char* rowB = pBh + (nt * 8 + g) * B_RS;
                const char* rowBl = pBl + (nt * 8 + g) * B_RS;
                uint32_t bh[2], bl[2];
                bh[0] = *(const uint32_t*)(rowB + koff);
                bh[1] = *(const uint32_t*)(rowB + koff + 16);
                bl[0] = *(const uint32_t*)(rowBl + koff);
                bl[1] = *(const uint32_t*)(rowBl + koff + 16);
                mma_bf16(acc[nt], ah, bh);
                mma_bf16(acc[nt], ah, bl);
                mma_bf16(acc[nt], al, bh);
            }
        }
        __syncthreads();
    }

    // ---- epilogue: bias + silu + atomic scatter
    {
        int r0 = w * 16 + g, r1 = r0 + 8;
        int d0 = s_dst[r0], d1 = s_dst[r1];
        float* agg0 = g_agg + (size_t)d0 * 64;
        float* agg1 = g_agg + (size_t)d1 * 64;
#pragma unroll
        for (int nt = 0; nt < 8; ++nt) {
            int c0 = nt * 8 + 2 * t, c1 = c0 + 1;
            atomicAdd(agg0 + c0, silu_f(acc[nt][0] + s_b2[c0]));
            atomicAdd(agg0 + c1, silu_f(acc[nt][1] + s_b2[c1]));
            atomicAdd(agg1 + c0, silu_f(acc[nt][2] + s_b2[c0]));
            atomicAdd(agg1 + c1, silu_f(acc[nt][3] + s_b2[c1]));
        }
    }
}

// ================= embed kernel v4 (unchanged) ==============================
#define E4_OFF_W  0
#define E4_OFF_IN 8704
#define E4_OFF_A  (8704 + 1344)
#define E4_FLOATS (8704 + 1344 + 512)
#define E4_BYTES  (E4_FLOATS * 4)

__global__ void __launch_bounds__(128, 2)
embed_kernel_v4(const float* __restrict__ x, const float* __restrict__ anf,
                const float* __restrict__ node_attr,
                const float* __restrict__ W_emb, const float* __restrict__ b_emb)
{
    extern __shared__ float sm[];
    float* s_W  = sm + E4_OFF_W;
    float* s_in = sm + E4_OFF_IN;
    float* s_a  = sm + E4_OFF_A;

    int tid = threadIdx.x;
    int wid = tid >> 5, lane = tid & 31;
    int n0 = blockIdx.x * 64;

    stage_w128(s_W, W_emb, 0, 17);
    for (int row = wid; row < 64; row += 4) {
        int n = min(n0 + row, NN - 1);
        if (lane < 17)
            s_in[row * 21 + lane] = (lane < 16) ? x[n * 16 + lane] : anf[n];
        if (lane < 8)
            s_a[row * 8 + lane] = node_attr[n * 8 + lane];
    }
    __syncthreads();

    int ng = tid >> 3, kq = tid & 7;
    int nrow0 = ng * 4, kbase = kq * 8;

    float av[4][8];
#pragma unroll
    for (int s = 0; s < 4; ++s)
#pragma unroll
        for (int j = 0; j < 8; ++j) av[s][j] = s_a[(nrow0 + s) * 8 + j];

    float acc[4][8];
#pragma unroll
    for (int t = 0; t < 8; ++t) {
        float b = b_emb[kbase + t];
        acc[0][t] = b; acc[1][t] = b; acc[2][t] = b; acc[3][t] = b;
    }

    tp4(acc, s_in, 21, s_W, av, nrow0, kbase, 17);

#pragma unroll
    for (int s = 0; s < 4; ++s) {
        int n = n0 + nrow0 + s;
        if (n < NN) {
#pragma unroll
            for (int t = 0; t < 8; ++t) g_h[n * 64 + kbase + t] = acc[s][t];
        }
    }
}

// ================= upd kernel v4 (unchanged) ================================
#define U4_OFF_W   0
#define U4_OFF_IN  8192
#define U4_OFF_MID (8192 + 8512)
#define U4_OFF_A   (8192 + 8512 + 4288)
#define U4_FLOATS  (8192 + 8512 + 4288 + 512)
#define U4_BYTES   (U4_FLOATS * 4)

__global__ void __launch_bounds__(128, 2)
upd_kernel_v4(int l, const float* __restrict__ node_attr, const float* __restrict__ anf,
              const float* __restrict__ Wu1, const float* __restrict__ bu1,
              const float* __restrict__ Wu2, const float* __restrict__ bu2)
{
    extern __shared__ float sm[];
    float* s_W   = sm + U4_OFF_W;
    float* s_in  = sm + U4_OFF_IN;
    float* s_mid = sm + U4_OFF_MID;
    float* s_a   = sm + U4_OFF_A;

    int tid = threadIdx.x;
    int wid = tid >> 5, lane = tid & 31;
    int n0 = blockIdx.x * 64;

    for (int row = wid; row < 64; row += 4) {
        int n = min(n0 + row, NN - 1);
        float* dst = s_in + row * 133;
        for (int i = lane; i < UPDIN; i += 32) {
            float v;
            if (i < 64) v = g_h[n * 64 + i];
            else if (i == 64) v = anf[n];
            else v = g_agg[n * 64 + (i - 65)];
            dst[i] = v;
        }
        if (lane < 8) s_a[row * 8 + lane] = node_attr[n * 8 + lane];
    }

    int ng = tid >> 3, kq = tid & 7;
    int nrow0 = ng * 4, kbase = kq * 8;
    const float* W1 = Wu1 + (size_t)l * UPDIN * 512;
    const float* W2 = Wu2 + (size_t)l * 64 * 512;

    __syncthreads();
    float av[4][8];
#pragma unroll
    for (int s = 0; s < 4; ++s)
#pragma unroll
        for (int j = 0; j < 8; ++j) av[s][j] = s_a[(nrow0 + s) * 8 + j];

    float acc[4][8];
#pragma unroll
    for (int t = 0; t < 8; ++t) {
        float b = bu1[l * 64 + kbase + t];
        acc[0][t] = b; acc[1][t] = b; acc[2][t] = b; acc[3][t] = b;
    }

    for (int ibase = 0; ibase < UPDIN; ibase += 16) {
        int ilen = min(16, UPDIN - ibase);
        __syncthreads();
        stage_w128(s_W, W1, ibase, ilen);
        __syncthreads();
        tp4(acc, s_in + ibase, 133, s_W, av, nrow0, kbase, ilen);
    }

#pragma unroll
    for (int s = 0; s < 4; ++s)
#pragma unroll
        for (int t = 0; t < 8; ++t)
            s_mid[(nrow0 + s) * 67 + kbase + t] = silu_f(acc[s][t]);

#pragma unroll
    for (int t = 0; t < 8; ++t) {
        float b = bu2[l * 64 + kbase + t];
        acc[0][t] = b; acc[1][t] = b; acc[2][t] = b; acc[3][t] = b;
    }

    for (int ibase = 0; ibase < 64; ibase += 16) {
        __syncthreads();
        stage_w128(s_W, W2, ibase, 16);
        __syncthreads();
        tp4(acc, s_mid + ibase, 67, s_W, av, nrow0, kbase, 16);
    }

#pragma unroll
    for (int s = 0; s < 4; ++s) {
        int n = n0 + nrow0 + s;
        if (n < NN) {
#pragma unroll
            for (int t = 0; t < 8; ++t)
                g_h[n * 64 + kbase + t] += acc[s][t];
        }
    }
}

// ================= pool kernel v4 (unchanged) ===============================
#define P4_OFF_W   0
#define P4_OFF_IN  8192
#define P4_OFF_MID (8192 + 4288)
#define P4_OFF_A   (8192 + 4288 + 4288)
#define P4_FLOATS  (8192 + 4288 + 4288 + 512)
#define P4_BYTES   (P4_FLOATS * 4)

__global__ void __launch_bounds__(128, 2)
pool_kernel_v4(const float* __restrict__ node_attr, const int* __restrict__ batch,
               const float* __restrict__ Wp1, const float* __restrict__ bp1,
               const float* __restrict__ Wp2, const float* __restrict__ bp2)
{
    extern __shared__ float sm[];
    float* s_W   = sm + P4_OFF_W;
    float* s_in  = sm + P4_OFF_IN;
    float* s_mid = sm + P4_OFF_MID;
    float* s_a   = sm + P4_OFF_A;

    int tid = threadIdx.x;
    int wid = tid >> 5, lane = tid & 31;
    int n0 = blockIdx.x * 64;

    for (int row = wid; row < 64; row += 4) {
        int n = min(n0 + row, NN - 1);
        for (int i = lane; i < 64; i += 32)
            s_in[row * 67 + i] = g_h[n * 64 + i];
        if (lane < 8) s_a[row * 8 + lane] = node_attr[n * 8 + lane];
    }

    int ng = tid >> 3, kq = tid & 7;
    int nrow0 = ng * 4, kbase = kq * 8;

    __syncthreads();
    float av[4][8];
#pragma unroll
    for (int s = 0; s < 4; ++s)
#pragma unroll
        for (int j = 0; j < 8; ++j) av[s][j] = s_a[(nrow0 + s) * 8 + j];

    float acc[4][8];
#pragma unroll
    for (int t = 0; t < 8; ++t) {
        float b = bp1[kbase + t];
        acc[0][t] = b; acc[1][t] = b; acc[2][t] = b; acc[3][t] = b;
    }

    for (int ibase = 0; ibase < 64; ibase += 16) {
        __syncthreads();
        stage_w128(s_W, Wp1, ibase, 16);
        __syncthreads();
        tp4(acc, s_in + ibase, 67, s_W, av, nrow0, kbase, 16);
    }

#pragma unroll
    for (int s = 0; s < 4; ++s)
#pragma unroll
        for (int t = 0; t < 8; ++t)
            s_mid[(nrow0 + s) * 67 + kbase + t] = silu_f(acc[s][t]);

#pragma unroll
    for (int t = 0; t < 8; ++t) {
        float b = bp2[kbase + t];
        acc[0][t] = b; acc[1][t] = b; acc[2][t] = b; acc[3][t] = b;
    }

    for (int ibase = 0; ibase < 64; ibase += 16) {
        __syncthreads();
        stage_w128(s_W, Wp2, ibase, 16);
        __syncthreads();
        tp4(acc, s_mid + ibase, 67, s_W, av, nrow0, kbase, 16);
    }

#pragma unroll
    for (int s = 0; s < 4; ++s) {
        int n = n0 + nrow0 + s;
        if (n < NN) {
            int b = batch[n];
#pragma unroll
            for (int t = 0; t < 8; ++t)
                atomicAdd(&g_pool[b * 64 + kbase + t], acc[s][t]);
            if (kq == 0) atomicAdd(&g_cnt[b], 1.0f);
        }
    }
}

// ---------------- final tiny post-pool MLP ---------------------------------
__global__ void final_kernel(const float* __restrict__ Wq1, const float* __restrict__ bq1,
                             const float* __restrict__ Wq2, const float* __restrict__ bq2,
                             float* __restrict__ out)
{
    int b = threadIdx.x;
    if (b >= BB) return;
    float c = g_cnt[b];
    if (c < 1.0f) c = 1.0f;
    float g[64];
#pragma unroll
    for (int k = 0; k < 64; ++k) g[k] = g_pool[b * 64 + k] / c;
    float o = bq2[0];
    for (int j = 0; j < 64; ++j) {
        float s = bq1[j];
#pragma unroll
        for (int k = 0; k < 64; ++k) s = fmaf(g[k], Wq1[k * 64 + j], s);
        o = fmaf(silu_f(s), Wq2[j], o);
    }
    out[b] = o;
}

// ---------------- launch ----------------------------------------------------
extern "C" void kernel_launch(void* const* d_in, const int* in_sizes, int n_in,
                              void* d_out, int out_size)
{
    const float* x         = (const float*)d_in[0];
    const int*   edge_index= (const int*)d_in[1];
    const float* edge_attr = (const float*)d_in[2];
    const float* node_attr = (const float*)d_in[3];
    const float* amf       = (const float*)d_in[4];
    const float* anf       = (const float*)d_in[5];
    const int*   batch     = (const int*)d_in[6];
    const float* W_emb     = (const float*)d_in[7];
    const float* b_emb     = (const float*)d_in[8];
    const float* Wm1       = (const float*)d_in[9];
    const float* bm1       = (const float*)d_in[10];
    const float* Wm2       = (const float*)d_in[11];
    const float* bm2       = (const float*)d_in[12];
    const float* Wu1       = (const float*)d_in[13];
    const float* bu1       = (const float*)d_in[14];
    const float* Wu2       = (const float*)d_in[15];
    const float* bu2       = (const float*)d_in[16];
    const float* Wp1       = (const float*)d_in[17];
    const float* bp1       = (const float*)d_in[18];
    const float* Wp2       = (const float*)d_in[19];
    const float* bp2       = (const float*)d_in[20];
    const float* Wq1       = (const float*)d_in[21];
    const float* bq1       = (const float*)d_in[22];
    const float* Wq2       = (const float*)d_in[23];
    const float* bq2       = (const float*)d_in[24];
    float* out = (float*)d_out;

    cudaFuncSetAttribute(msg_kernel_mma,  cudaFuncAttributeMaxDynamicSharedMemorySize, MG_BYTES);
    cudaFuncSetAttribute(nodeT_kernel,    cudaFuncAttributeMaxDynamicSharedMemorySize, NT_BYTES);
    cudaFuncSetAttribute(embed_kernel_v4, cudaFuncAttributeMaxDynamicSharedMemorySize, E4_BYTES);
    cudaFuncSetAttribute(upd_kernel_v4,   cudaFuncAttributeMaxDynamicSharedMemorySize, U4_BYTES);
    cudaFuncSetAttribute(pool_kernel_v4,  cudaFuncAttributeMaxDynamicSharedMemorySize, P4_BYTES);

    void* aggp = nullptr;  cudaGetSymbolAddress(&aggp, g_agg);
    void* poolp = nullptr; cudaGetSymbolAddress(&poolp, g_pool);
    void* cntp = nullptr;  cudaGetSymbolAddress(&cntp, g_cnt);

    int tblocks = (NN + 63) / 64;     // 157
    int eblocks = EE / 128;           // 1250

    embed_kernel_v4<<<tblocks, 128, E4_BYTES>>>(x, anf, node_attr, W_emb, b_emb);

    for (int l = 0; l < LL; ++l) {
        nodeT_kernel<<<tblocks, 256, NT_BYTES>>>(l, anf, Wm1);
        cudaMemsetAsync(aggp, 0, (size_t)NN * HH * sizeof(float));
        msg_kernel_mma<<<eblocks, 256, MG_BYTES>>>(l, edge_index, edge_attr, amf,
                                                   Wm1, bm1, Wm2, bm2);
        upd_kernel_v4<<<tblocks, 128, U4_BYTES>>>(l, node_attr, anf, Wu1, bu1, Wu2, bu2);
    }

    cudaMemsetAsync(poolp, 0, (size_t)BB * HH * sizeof(float));
    cudaMemsetAsync(cntp, 0, (size_t)BB * sizeof(float));
    pool_kernel_v4<<<tblocks, 128, P4_BYTES>>>(node_attr, batch, Wp1, bp1, Wp2, bp2);
    final_kernel<<<1, BB>>>(Wq1, bq1, Wq2, bq2, out);
}